// round 5
// baseline (speedup 1.0000x reference)
#include <cuda_runtime.h>
#include <math.h>

// ---------------------------------------------------------------------------
// Problem constants
// ---------------------------------------------------------------------------
#define D_MODEL 1024
#define SEQ     2048
#define BATCH   2
#define NHEADS  16
#define HDIM    64
#define MTOK    (BATCH*SEQ)        // 4096 token rows
#define DFF     (4*D_MODEL)        // 4096

// ---------------------------------------------------------------------------
// Scratch (device globals: allocation-free contract)
// ---------------------------------------------------------------------------
__device__ float g_ln  [MTOK*D_MODEL];            // LN output (reused for ln1/ln2)
__device__ float g_q   [MTOK*D_MODEL];
__device__ float g_k   [MTOK*D_MODEL];
__device__ float g_v   [MTOK*D_MODEL];
__device__ float g_pre [MTOK*D_MODEL];            // attention pre-output (B,S,H,hd)
__device__ float g_x1  [MTOK*D_MODEL];            // x + attn
__device__ float g_mid [MTOK*DFF];                // gelu(ln2 @ Wup^T)
__device__ float g_logits[(long long)BATCH*NHEADS*SEQ*SEQ]; // 512 MB

// ---------------------------------------------------------------------------
// Helpers
// ---------------------------------------------------------------------------
__device__ __forceinline__ unsigned f2tf(float x) {
    unsigned u; asm("cvt.rna.tf32.f32 %0, %1;" : "=r"(u) : "f"(x)); return u;
}
__device__ __forceinline__ float geluf(float x) {
    return 0.5f * x * (1.0f + erff(x * 0.7071067811865475f));
}
__device__ __forceinline__ void mma8(float* d, const unsigned* a, const unsigned* b) {
    asm volatile(
        "mma.sync.aligned.m16n8k8.row.col.f32.tf32.tf32.f32 "
        "{%0,%1,%2,%3}, {%4,%5,%6,%7}, {%8,%9}, {%0,%1,%2,%3};\n"
        : "+f"(d[0]), "+f"(d[1]), "+f"(d[2]), "+f"(d[3])
        : "r"(a[0]), "r"(a[1]), "r"(a[2]), "r"(a[3]), "r"(b[0]), "r"(b[1]));
}
__device__ __forceinline__ float warpsum(float x) {
    #pragma unroll
    for (int o = 16; o; o >>= 1) x += __shfl_xor_sync(0xffffffffu, x, o);
    return x;
}
__device__ __forceinline__ float warpmax(float x) {
    #pragma unroll
    for (int o = 16; o; o >>= 1) x = fmaxf(x, __shfl_xor_sync(0xffffffffu, x, o));
    return x;
}

#define EPI_NONE 0
#define EPI_RES  1
#define EPI_GELU 2

// ---------------------------------------------------------------------------
// tf32 GEMM:  C = alpha * A(MxK) * op(B) [+ Res]
//   BNT=true : B is [N][K] row-major (NT, i.e. x @ W^T)
//   BNT=false: B is [K][N] row-major (NN, used for P@V)
// Batched over blockIdx.z with split strides: off = (z/ZH)*s1 + (z%ZH)*s2.
// All tile dims divide problem dims exactly (no bounds guards).
// ---------------------------------------------------------------------------
template<int BM, int BN, int WM, int WN, bool BNT, int EPI>
__global__ void __launch_bounds__(256)
gemm_tf32(const float* __restrict__ A, const float* __restrict__ B,
          float* __restrict__ C, const float* __restrict__ R,
          int K, int lda, int ldb, int ldc, int ZH,
          long long sA1, long long sA2, long long sB1, long long sB2,
          long long sC1, long long sC2, float alpha)
{
    constexpr int BKq  = 16;
    constexpr int AST  = BKq + 4;          // 20: K-major tile row stride (conflict-free frags)
    constexpr int BSTN = BN + 8;           // NN tile row stride (conflict-free frags)
    constexpr int MT   = WM / 16;
    constexpr int NTL  = WN / 8;
    constexpr int AVEC = BM * BKq / (4 * 256);
    constexpr int BVEC = (BNT ? BN * BKq : BKq * BN) / (4 * 256);

    __shared__ unsigned sA[2][BM * AST];
    __shared__ unsigned sB[2][BNT ? BN * AST : BKq * BSTN];

    const int z = blockIdx.z;
    const long long zb = z / ZH, zh = z % ZH;
    A += zb * sA1 + zh * sA2;
    B += zb * sB1 + zh * sB2;
    C += zb * sC1 + zh * sC2;
    if (EPI == EPI_RES) R += zb * sC1 + zh * sC2;

    const int tid = threadIdx.x, lane = tid & 31, wid = tid >> 5;
    constexpr int WROWS = BM / WM;
    const int wm = wid % WROWS, wn = wid / WROWS;
    const int bm0 = blockIdx.y * BM, bn0 = blockIdx.x * BN;

    float4 rA[AVEC], rB[BVEC];

    auto ldg = [&](int kt) {
        #pragma unroll
        for (int i = 0; i < AVEC; i++) {
            int f = tid + i * 256; int r = f >> 2, cv = f & 3;
            rA[i] = *reinterpret_cast<const float4*>(
                A + (long long)(bm0 + r) * lda + kt * BKq + 4 * cv);
        }
        #pragma unroll
        for (int i = 0; i < BVEC; i++) {
            int f = tid + i * 256;
            if (BNT) {
                int r = f >> 2, cv = f & 3;
                rB[i] = *reinterpret_cast<const float4*>(
                    B + (long long)(bn0 + r) * ldb + kt * BKq + 4 * cv);
            } else {
                int r = f / (BN / 4), cv = f % (BN / 4);
                rB[i] = *reinterpret_cast<const float4*>(
                    B + (long long)(kt * BKq + r) * ldb + bn0 + 4 * cv);
            }
        }
    };
    auto sts = [&](int bufi) {
        #pragma unroll
        for (int i = 0; i < AVEC; i++) {
            int f = tid + i * 256; int r = f >> 2, cv = f & 3;
            unsigned* d = &sA[bufi][r * AST + 4 * cv];
            d[0] = f2tf(rA[i].x); d[1] = f2tf(rA[i].y);
            d[2] = f2tf(rA[i].z); d[3] = f2tf(rA[i].w);
        }
        #pragma unroll
        for (int i = 0; i < BVEC; i++) {
            int f = tid + i * 256;
            unsigned* d;
            if (BNT) { int r = f >> 2, cv = f & 3; d = &sB[bufi][r * AST + 4 * cv]; }
            else     { int r = f / (BN / 4), cv = f % (BN / 4); d = &sB[bufi][r * BSTN + 4 * cv]; }
            d[0] = f2tf(rB[i].x); d[1] = f2tf(rB[i].y);
            d[2] = f2tf(rB[i].z); d[3] = f2tf(rB[i].w);
        }
    };

    float acc[MT][NTL][4];
    #pragma unroll
    for (int a = 0; a < MT; a++)
        #pragma unroll
        for (int b = 0; b < NTL; b++)
            #pragma unroll
            for (int c = 0; c < 4; c++) acc[a][b][c] = 0.f;

    const int nkt = K / BKq;
    const int g = lane >> 2, t4 = lane & 3;

    ldg(0); sts(0); __syncthreads();
    int buf = 0;
    for (int kt = 0; kt < nkt; kt++) {
        if (kt + 1 < nkt) ldg(kt + 1);
        #pragma unroll
        for (int kk = 0; kk < BKq; kk += 8) {
            unsigned af[MT][4], bfr[NTL][2];
            #pragma unroll
            for (int mt = 0; mt < MT; mt++) {
                const unsigned* p = &sA[buf][(wm * WM + mt * 16 + g) * AST + kk];
                af[mt][0] = p[t4];
                af[mt][1] = p[8 * AST + t4];
                af[mt][2] = p[t4 + 4];
                af[mt][3] = p[8 * AST + t4 + 4];
            }
            #pragma unroll
            for (int nt = 0; nt < NTL; nt++) {
                int col = wn * WN + nt * 8 + g;
                if (BNT) {
                    const unsigned* p = &sB[buf][col * AST + kk];
                    bfr[nt][0] = p[t4];
                    bfr[nt][1] = p[t4 + 4];
                } else {
                    bfr[nt][0] = sB[buf][(kk + t4) * BSTN + col];
                    bfr[nt][1] = sB[buf][(kk + t4 + 4) * BSTN + col];
                }
            }
            #pragma unroll
            for (int mt = 0; mt < MT; mt++)
                #pragma unroll
                for (int nt = 0; nt < NTL; nt++)
                    mma8(acc[mt][nt], af[mt], bfr[nt]);
        }
        if (kt + 1 < nkt) sts(buf ^ 1);
        __syncthreads();
        buf ^= 1;
    }

    // Epilogue: c0,c1 at (row, 2*t4 .. +1); c2,c3 at row+8.
    #pragma unroll
    for (int mt = 0; mt < MT; mt++) {
        #pragma unroll
        for (int nt = 0; nt < NTL; nt++) {
            int cm = bm0 + wm * WM + mt * 16 + g;
            int cn = bn0 + wn * WN + nt * 8 + 2 * t4;
            #pragma unroll
            for (int h = 0; h < 2; h++) {
                long long idx = (long long)(cm + 8 * h) * ldc + cn;
                float vx = alpha * acc[mt][nt][2 * h];
                float vy = alpha * acc[mt][nt][2 * h + 1];
                if (EPI == EPI_RES) {
                    float2 r2 = *reinterpret_cast<const float2*>(R + idx);
                    vx += r2.x; vy += r2.y;
                }
                if (EPI == EPI_GELU) { vx = geluf(vx); vy = geluf(vy); }
                float2 o; o.x = vx; o.y = vy;
                *reinterpret_cast<float2*>(C + idx) = o;
            }
        }
    }
}

// ---------------------------------------------------------------------------
// LayerNorm (torch-style: unbiased var, eps inside sqrt): one block per row.
// ---------------------------------------------------------------------------
__global__ void __launch_bounds__(256)
ln_kernel(const float* __restrict__ X, float* __restrict__ Y,
          const float* __restrict__ MS, const float* __restrict__ SS)
{
    __shared__ float shs[8], shq[8];
    const int tid = threadIdx.x;
    const long long base = (long long)blockIdx.x * D_MODEL;
    float4 v = reinterpret_cast<const float4*>(X + base)[tid];
    float s = v.x + v.y + v.z + v.w;
    float q = v.x * v.x + v.y * v.y + v.z * v.z + v.w * v.w;
    s = warpsum(s); q = warpsum(q);
    if ((tid & 31) == 0) { shs[tid >> 5] = s; shq[tid >> 5] = q; }
    __syncthreads();
    float ts = 0.f, tq = 0.f;
    #pragma unroll
    for (int i = 0; i < 8; i++) { ts += shs[i]; tq += shq[i]; }
    float mean = ts * (1.0f / D_MODEL);
    float var  = (tq - (float)D_MODEL * mean * mean) * (1.0f / (D_MODEL - 1));
    float rstd = rsqrtf(var + 1e-9f);
    float4 ms = reinterpret_cast<const float4*>(MS)[tid];
    float4 ss = reinterpret_cast<const float4*>(SS)[tid];
    float4 o;
    o.x = (v.x - mean) * rstd * ss.x + ms.x;
    o.y = (v.y - mean) * rstd * ss.y + ms.y;
    o.z = (v.z - mean) * rstd * ss.z + ms.z;
    o.w = (v.w - mean) * rstd * ss.w + ms.w;
    reinterpret_cast<float4*>(Y + base)[tid] = o;
}

// ---------------------------------------------------------------------------
// Causal softmax, in place, one block per row (row = bh*SEQ + s).
// Register-resident: 1 read + 1 write of the 2048-wide row.
// ---------------------------------------------------------------------------
__global__ void __launch_bounds__(256)
softmax_causal_kernel(float* __restrict__ P)
{
    __shared__ float sh[8];
    const long long row = blockIdx.x;
    const int s = (int)(row & (SEQ - 1));
    const int L = s + 1;
    float* p = P + row * (long long)SEQ;
    const int tid = threadIdx.x;

    float v[8];
    float m = -1e30f;
    #pragma unroll
    for (int i = 0; i < 8; i++) {
        int j = tid + i * 256;
        v[i] = (j < L) ? p[j] : -1e30f;
        m = fmaxf(m, v[i]);
    }
    m = warpmax(m);
    if ((tid & 31) == 0) sh[tid >> 5] = m;
    __syncthreads();
    #pragma unroll
    for (int i = 0; i < 8; i++) m = fmaxf(m, sh[i]);
    __syncthreads();

    float sum = 0.f;
    #pragma unroll
    for (int i = 0; i < 8; i++) {
        int j = tid + i * 256;
        v[i] = (j < L) ? __expf(v[i] - m) : 0.f;
        sum += v[i];
    }
    sum = warpsum(sum);
    if ((tid & 31) == 0) sh[tid >> 5] = sum;
    __syncthreads();
    float tsum = 0.f;
    #pragma unroll
    for (int i = 0; i < 8; i++) tsum += sh[i];
    float rinv = 1.0f / tsum;
    #pragma unroll
    for (int i = 0; i < 8; i++) p[tid + i * 256] = v[i] * rinv;
}

// ---------------------------------------------------------------------------
// kernel_launch
// ---------------------------------------------------------------------------
extern "C" void kernel_launch(void* const* d_in, const int* in_sizes, int n_in,
                              void* d_out, int out_size)
{
    const float* x     = (const float*)d_in[0];
    const float* Wq    = (const float*)d_in[1];
    const float* Wk    = (const float*)d_in[2];
    const float* Wv    = (const float*)d_in[3];
    const float* Wo    = (const float*)d_in[4];
    const float* Wup   = (const float*)d_in[5];
    const float* Wdown = (const float*)d_in[6];
    const float* m1    = (const float*)d_in[7];
    const float* s1    = (const float*)d_in[8];
    const float* m2    = (const float*)d_in[9];
    const float* s2    = (const float*)d_in[10];
    float* out = (float*)d_out;

    float *ln, *q, *k, *v, *pre, *x1, *mid, *lg;
    cudaGetSymbolAddress((void**)&ln,  g_ln);
    cudaGetSymbolAddress((void**)&q,   g_q);
    cudaGetSymbolAddress((void**)&k,   g_k);
    cudaGetSymbolAddress((void**)&v,   g_v);
    cudaGetSymbolAddress((void**)&pre, g_pre);
    cudaGetSymbolAddress((void**)&x1,  g_x1);
    cudaGetSymbolAddress((void**)&mid, g_mid);
    cudaGetSymbolAddress((void**)&lg,  g_logits);

    const long long SS2 = (long long)SEQ * SEQ;
    const long long TOKD = (long long)SEQ * D_MODEL;   // per-batch token-row stride

    // 1) LN1
    ln_kernel<<<MTOK, 256>>>(x, ln, m1, s1);

    // 2) Q/K/V = ln @ W^T   (M=4096, N=1024, K=1024)
    dim3 gqkv(D_MODEL / 128, MTOK / 128, 1);
    gemm_tf32<128,128,32,64,true,EPI_NONE><<<gqkv, 256>>>(
        ln, Wq, q, nullptr, D_MODEL, D_MODEL, D_MODEL, D_MODEL,
        1, 0,0, 0,0, 0,0, 1.0f);
    gemm_tf32<128,128,32,64,true,EPI_NONE><<<gqkv, 256>>>(
        ln, Wk, k, nullptr, D_MODEL, D_MODEL, D_MODEL, D_MODEL,
        1, 0,0, 0,0, 0,0, 1.0f);
    gemm_tf32<128,128,32,64,true,EPI_NONE><<<gqkv, 256>>>(
        ln, Wv, v, nullptr, D_MODEL, D_MODEL, D_MODEL, D_MODEL,
        1, 0,0, 0,0, 0,0, 1.0f);

    // 3) logits[bh] = (Q_bh @ K_bh^T) / 8   (z = b*16 + h, 32 batches)
    dim3 glog(SEQ / 128, SEQ / 128, BATCH * NHEADS);
    gemm_tf32<128,128,32,64,true,EPI_NONE><<<glog, 256>>>(
        q, k, lg, nullptr, HDIM, D_MODEL, D_MODEL, SEQ,
        NHEADS,
        TOKD, (long long)HDIM,              // A (Q): batch stride, head stride
        TOKD, (long long)HDIM,              // B (K)
        (long long)NHEADS * SS2, SS2,       // C (logits)
        0.125f);

    // 4) causal softmax in place
    softmax_causal_kernel<<<BATCH * NHEADS * SEQ, 256>>>(lg);

    // 5) pre[bh] = P_bh @ V_bh   (NN, M=2048, N=64, K=2048)
    dim3 gpv(HDIM / 64, SEQ / 128, BATCH * NHEADS);
    gemm_tf32<128,64,32,32,false,EPI_NONE><<<gpv, 256>>>(
        lg, v, pre, nullptr, SEQ, SEQ, D_MODEL, D_MODEL,
        NHEADS,
        (long long)NHEADS * SS2, SS2,       // A (P)
        TOKD, (long long)HDIM,              // B (V)
        TOKD, (long long)HDIM,              // C (pre, interleaved back to [tok, D])
        1.0f);

    // 6) x1 = x + pre @ Wo^T
    gemm_tf32<128,128,32,64,true,EPI_RES><<<gqkv, 256>>>(
        pre, Wo, x1, x, D_MODEL, D_MODEL, D_MODEL, D_MODEL,
        1, 0,0, 0,0, 0,0, 1.0f);

    // 7) LN2
    ln_kernel<<<MTOK, 256>>>(x1, ln, m2, s2);

    // 8) mid = gelu(ln2 @ Wup^T)   (M=4096, N=4096, K=1024)
    dim3 gup(DFF / 128, MTOK / 128, 1);
    gemm_tf32<128,128,32,64,true,EPI_GELU><<<gup, 256>>>(
        ln, Wup, mid, nullptr, D_MODEL, D_MODEL, D_MODEL, DFF,
        1, 0,0, 0,0, 0,0, 1.0f);

    // 9) out = x1 + mid @ Wdown^T   (M=4096, N=1024, K=4096)
    gemm_tf32<128,128,32,64,true,EPI_RES><<<gqkv, 256>>>(
        mid, Wdown, out, x1, DFF, DFF, DFF, D_MODEL,
        1, 0,0, 0,0, 0,0, 1.0f);
}

// round 8
// speedup vs baseline: 1.2945x; 1.2945x over previous
#include <cuda_runtime.h>
#include <math.h>

// ---------------------------------------------------------------------------
// Problem constants
// ---------------------------------------------------------------------------
#define D_MODEL 1024
#define SEQ     2048
#define BATCH   2
#define NHEADS  16
#define HDIM    64
#define MTOK    (BATCH*SEQ)        // 4096 token rows
#define DFF     (4*D_MODEL)        // 4096

// ---------------------------------------------------------------------------
// Scratch (device globals: allocation-free contract)
// ---------------------------------------------------------------------------
__device__ float g_ln  [MTOK*D_MODEL];
__device__ float g_qkv [3*MTOK*D_MODEL];          // q | k | v contiguous
__device__ float g_pre [MTOK*D_MODEL];
__device__ float g_x1  [MTOK*D_MODEL];
__device__ float g_mid [MTOK*DFF];
__device__ float g_logits[(long long)BATCH*NHEADS*SEQ*SEQ]; // 512 MB
// tf32-rounded weights: Wq,Wk,Wv (contiguous), Wo, Wup, Wdown
__device__ float g_wr[4*D_MODEL*D_MODEL + 2*(long long)DFF*D_MODEL];

// ---------------------------------------------------------------------------
// Helpers
// ---------------------------------------------------------------------------
__device__ __forceinline__ unsigned f2tf(float x) {
    unsigned u; asm("cvt.rna.tf32.f32 %0, %1;" : "=r"(u) : "f"(x)); return u;
}
__device__ __forceinline__ float rnd_tf32(float x) { return __uint_as_float(f2tf(x)); }
__device__ __forceinline__ float geluf(float x) {
    return 0.5f * x * (1.0f + erff(x * 0.7071067811865475f));
}
__device__ __forceinline__ void mma8(float* d, const unsigned* a, const unsigned* b) {
    asm volatile(
        "mma.sync.aligned.m16n8k8.row.col.f32.tf32.tf32.f32 "
        "{%0,%1,%2,%3}, {%4,%5,%6,%7}, {%8,%9}, {%0,%1,%2,%3};\n"
        : "+f"(d[0]), "+f"(d[1]), "+f"(d[2]), "+f"(d[3])
        : "r"(a[0]), "r"(a[1]), "r"(a[2]), "r"(a[3]), "r"(b[0]), "r"(b[1]));
}
__device__ __forceinline__ void ldsm4(unsigned& r0, unsigned& r1, unsigned& r2,
                                      unsigned& r3, unsigned a) {
    asm volatile("ldmatrix.sync.aligned.m8n8.x4.shared.b16 {%0,%1,%2,%3}, [%4];"
                 : "=r"(r0), "=r"(r1), "=r"(r2), "=r"(r3) : "r"(a));
}
__device__ __forceinline__ void cpasync16(unsigned dst, const float* src) {
    asm volatile("cp.async.cg.shared.global [%0], [%1], 16;\n"
                 :: "r"(dst), "l"(src) : "memory");
}
__device__ __forceinline__ float warpsum(float x) {
    #pragma unroll
    for (int o = 16; o; o >>= 1) x += __shfl_xor_sync(0xffffffffu, x, o);
    return x;
}
__device__ __forceinline__ float warpmax(float x) {
    #pragma unroll
    for (int o = 16; o; o >>= 1) x = fmaxf(x, __shfl_xor_sync(0xffffffffu, x, o));
    return x;
}

#define EPI_NONE 0
#define EPI_RES  1
#define EPI_GELU 2

// ---------------------------------------------------------------------------
// tf32 GEMM:  C = alpha * A(MxK) * op(B) [+ Res]
//   BNT=true : B is [N][K] row-major (NT, x @ W^T)
//   BNT=false: B is [K][N] row-major (NN, P @ V)
// Inputs must already be tf32-rounded (producers round). cp.async 4-stage
// pipeline, ldmatrix.x4 fragment loads, padded conflict-free smem.
// RND: round outputs to tf32 in epilogue (when consumer is another GEMM).
// ---------------------------------------------------------------------------
template<int BM, int BN, int WM, int WN, bool BNT, int EPI, bool RND>
__global__ void __launch_bounds__(256, 2)
gemm_tf32(const float* __restrict__ A, const float* __restrict__ B,
          float* __restrict__ C, const float* __restrict__ R,
          int K, int lda, int ldb, int ldc, int ZH,
          long long sA1, long long sA2, long long sB1, long long sB2,
          long long sC1, long long sC2, float alpha)
{
    constexpr int BK   = 16;
    constexpr int AST  = BK + 4;           // 20 words: K-major row stride
    constexpr int BSTN = BN + 8;           // NN tile row stride
    constexpr int MT   = WM / 16;
    constexpr int NTL  = WN / 8;
    constexpr int SA_SZ = BM * AST;                         // words
    constexpr int SB_SZ = BNT ? BN * AST : BK * BSTN;       // words
    constexpr int STAGE_SZ = SA_SZ + SB_SZ;                 // words
    constexpr int STAGES = 4;
    constexpr int AVEC = BM * BK / (4 * 256);               // 16B chunks / thread
    constexpr int BVEC = (BNT ? BN * BK : BK * BN) / (4 * 256);

    extern __shared__ float smem[];
    const unsigned smem_base = (unsigned)__cvta_generic_to_shared(smem);

    const int z = blockIdx.z;
    const long long zb = z / ZH, zh = z % ZH;
    A += zb * sA1 + zh * sA2;
    B += zb * sB1 + zh * sB2;
    C += zb * sC1 + zh * sC2;
    if (EPI == EPI_RES) R += zb * sC1 + zh * sC2;

    const int tid = threadIdx.x, lane = tid & 31, wid = tid >> 5;
    constexpr int WROWS = BM / WM;
    const int wm = wid % WROWS, wn = wid / WROWS;
    const int bm0 = blockIdx.y * BM, bn0 = blockIdx.x * BN;
    const int nkt = K / BK;

    // --- async tile load ---
    auto issue = [&](int kt, int st) {
        const unsigned sa = smem_base + st * (STAGE_SZ * 4);
        #pragma unroll
        for (int i = 0; i < AVEC; i++) {
            int f = tid + i * 256; int r = f >> 2, c = f & 3;
            cpasync16(sa + (r * AST + 4 * c) * 4,
                      A + (long long)(bm0 + r) * lda + kt * BK + 4 * c);
        }
        const unsigned sb = sa + SA_SZ * 4;
        #pragma unroll
        for (int i = 0; i < BVEC; i++) {
            int f = tid + i * 256;
            if (BNT) {
                int r = f >> 2, c = f & 3;
                cpasync16(sb + (r * AST + 4 * c) * 4,
                          B + (long long)(bn0 + r) * ldb + kt * BK + 4 * c);
            } else {
                int r = f / (BN / 4), c = f % (BN / 4);
                cpasync16(sb + (r * BSTN + 4 * c) * 4,
                          B + (long long)(kt * BK + r) * ldb + bn0 + 4 * c);
            }
        }
    };

    // prologue: stages 0..STAGES-2 (nkt >= 4 for all instantiations)
    #pragma unroll
    for (int s = 0; s < STAGES - 1; s++) {
        issue(s, s);
        asm volatile("cp.async.commit_group;\n" ::: "memory");
    }

    // fragment smem byte offsets (stage-relative), ldmatrix quadrant mapping
    const int r8 = lane & 7, q = lane >> 3;
    const int g = lane >> 2, t4 = lane & 3;
    unsigned aoff[MT];
    #pragma unroll
    for (int mt = 0; mt < MT; mt++)
        aoff[mt] = ((wm * WM + mt * 16 + (q & 1) * 8 + r8) * AST + (q >> 1) * 4) * 4;
    unsigned boff[(NTL + 1) / 2];
    if (BNT) {
        #pragma unroll
        for (int p = 0; p < NTL / 2; p++)
            boff[p] = SA_SZ * 4 +
                ((wn * WN + p * 16 + (q >> 1) * 8 + r8) * AST + (q & 1) * 4) * 4;
    }

    float acc[MT][NTL][4];
    #pragma unroll
    for (int a = 0; a < MT; a++)
        #pragma unroll
        for (int b = 0; b < NTL; b++)
            #pragma unroll
            for (int c = 0; c < 4; c++) acc[a][b][c] = 0.f;

    for (int kt = 0; kt < nkt; kt++) {
        asm volatile("cp.async.wait_group %0;\n" :: "n"(STAGES - 2) : "memory");
        __syncthreads();
        if (kt + STAGES - 1 < nkt) issue(kt + STAGES - 1, (kt + STAGES - 1) % STAGES);
        asm volatile("cp.async.commit_group;\n" ::: "memory");

        const int st = kt % STAGES;
        const unsigned sa = smem_base + st * (STAGE_SZ * 4);
        const unsigned* sbw = reinterpret_cast<const unsigned*>(smem) +
                              st * STAGE_SZ + SA_SZ;          // NN scalar path

        #pragma unroll
        for (int kk = 0; kk < BK; kk += 8) {
            unsigned af[MT][4], bf[NTL][2];
            #pragma unroll
            for (int mt = 0; mt < MT; mt++)
                ldsm4(af[mt][0], af[mt][1], af[mt][2], af[mt][3],
                      sa + aoff[mt] + kk * 4);
            if (BNT) {
                #pragma unroll
                for (int p = 0; p < NTL / 2; p++)
                    ldsm4(bf[2 * p][0], bf[2 * p][1], bf[2 * p + 1][0], bf[2 * p + 1][1],
                          sa + boff[p] + kk * 4);
            } else {
                #pragma unroll
                for (int nt = 0; nt < NTL; nt++) {
                    int col = wn * WN + nt * 8 + g;
                    bf[nt][0] = sbw[(kk + t4) * BSTN + col];
                    bf[nt][1] = sbw[(kk + t4 + 4) * BSTN + col];
                }
            }
            #pragma unroll
            for (int mt = 0; mt < MT; mt++)
                #pragma unroll
                for (int nt = 0; nt < NTL; nt++)
                    mma8(acc[mt][nt], af[mt], bf[nt]);
        }
    }

    // Epilogue: c0,c1 at (row, 2*t4 .. +1); c2,c3 at row+8.
    #pragma unroll
    for (int mt = 0; mt < MT; mt++) {
        #pragma unroll
        for (int nt = 0; nt < NTL; nt++) {
            int cm = bm0 + wm * WM + mt * 16 + g;
            int cn = bn0 + wn * WN + nt * 8 + 2 * t4;
            #pragma unroll
            for (int h = 0; h < 2; h++) {
                long long idx = (long long)(cm + 8 * h) * ldc + cn;
                float vx = alpha * acc[mt][nt][2 * h];
                float vy = alpha * acc[mt][nt][2 * h + 1];
                if (EPI == EPI_RES) {
                    float2 r2 = *reinterpret_cast<const float2*>(R + idx);
                    vx += r2.x; vy += r2.y;
                }
                if (EPI == EPI_GELU) { vx = geluf(vx); vy = geluf(vy); }
                if (RND) { vx = rnd_tf32(vx); vy = rnd_tf32(vy); }
                float2 o; o.x = vx; o.y = vy;
                *reinterpret_cast<float2*>(C + idx) = o;
            }
        }
    }
}

// ---------------------------------------------------------------------------
// tf32 rounding pre-pass for weights (float4 per thread)
// ---------------------------------------------------------------------------
__global__ void __launch_bounds__(256)
round_tf32_kernel(const float* __restrict__ s, float* __restrict__ d)
{
    long long i = (long long)blockIdx.x * blockDim.x + threadIdx.x;
    float4 v = reinterpret_cast<const float4*>(s)[i];
    v.x = rnd_tf32(v.x); v.y = rnd_tf32(v.y);
    v.z = rnd_tf32(v.z); v.w = rnd_tf32(v.w);
    reinterpret_cast<float4*>(d)[i] = v;
}

// ---------------------------------------------------------------------------
// LayerNorm (torch-style unbiased var). Output tf32-rounded (feeds GEMMs only).
// ---------------------------------------------------------------------------
__global__ void __launch_bounds__(256)
ln_kernel(const float* __restrict__ X, float* __restrict__ Y,
          const float* __restrict__ MS, const float* __restrict__ SS)
{
    __shared__ float shs[8], shq[8];
    const int tid = threadIdx.x;
    const long long base = (long long)blockIdx.x * D_MODEL;
    float4 v = reinterpret_cast<const float4*>(X + base)[tid];
    float s = v.x + v.y + v.z + v.w;
    float qq = v.x * v.x + v.y * v.y + v.z * v.z + v.w * v.w;
    s = warpsum(s); qq = warpsum(qq);
    if ((tid & 31) == 0) { shs[tid >> 5] = s; shq[tid >> 5] = qq; }
    __syncthreads();
    float ts = 0.f, tq = 0.f;
    #pragma unroll
    for (int i = 0; i < 8; i++) { ts += shs[i]; tq += shq[i]; }
    float mean = ts * (1.0f / D_MODEL);
    float var  = (tq - (float)D_MODEL * mean * mean) * (1.0f / (D_MODEL - 1));
    float rstd = rsqrtf(var + 1e-9f);
    float4 ms = reinterpret_cast<const float4*>(MS)[tid];
    float4 ss = reinterpret_cast<const float4*>(SS)[tid];
    float4 o;
    o.x = rnd_tf32((v.x - mean) * rstd * ss.x + ms.x);
    o.y = rnd_tf32((v.y - mean) * rstd * ss.y + ms.y);
    o.z = rnd_tf32((v.z - mean) * rstd * ss.z + ms.z);
    o.w = rnd_tf32((v.w - mean) * rstd * ss.w + ms.w);
    reinterpret_cast<float4*>(Y + base)[tid] = o;
}

// ---------------------------------------------------------------------------
// Causal softmax, in place; output tf32-rounded (feeds PV GEMM only).
// ---------------------------------------------------------------------------
__global__ void __launch_bounds__(256)
softmax_causal_kernel(float* __restrict__ P)
{
    __shared__ float sh[8];
    const long long row = blockIdx.x;
    const int s = (int)(row & (SEQ - 1));
    const int L = s + 1;
    float* p = P + row * (long long)SEQ;
    const int tid = threadIdx.x;

    float v[8];
    float m = -1e30f;
    #pragma unroll
    for (int i = 0; i < 8; i++) {
        int j = tid + i * 256;
        v[i] = (j < L) ? p[j] : -1e30f;
        m = fmaxf(m, v[i]);
    }
    m = warpmax(m);
    if ((tid & 31) == 0) sh[tid >> 5] = m;
    __syncthreads();
    #pragma unroll
    for (int i = 0; i < 8; i++) m = fmaxf(m, sh[i]);
    __syncthreads();

    float sum = 0.f;
    #pragma unroll
    for (int i = 0; i < 8; i++) {
        int j = tid + i * 256;
        v[i] = (j < L) ? __expf(v[i] - m) : 0.f;
        sum += v[i];
    }
    sum = warpsum(sum);
    if ((tid & 31) == 0) sh[tid >> 5] = sum;
    __syncthreads();
    float tsum = 0.f;
    #pragma unroll
    for (int i = 0; i < 8; i++) tsum += sh[i];
    float rinv = 1.0f / tsum;
    #pragma unroll
    for (int i = 0; i < 8; i++) p[tid + i * 256] = rnd_tf32(v[i] * rinv);
}

// ---------------------------------------------------------------------------
// kernel_launch
// ---------------------------------------------------------------------------
extern "C" void kernel_launch(void* const* d_in, const int* in_sizes, int n_in,
                              void* d_out, int out_size)
{
    const float* x     = (const float*)d_in[0];
    const float* Wq    = (const float*)d_in[1];
    const float* Wk    = (const float*)d_in[2];
    const float* Wv    = (const float*)d_in[3];
    const float* Wo    = (const float*)d_in[4];
    const float* Wup   = (const float*)d_in[5];
    const float* Wdown = (const float*)d_in[6];
    const float* m1    = (const float*)d_in[7];
    const float* s1    = (const float*)d_in[8];
    const float* m2    = (const float*)d_in[9];
    const float* s2    = (const float*)d_in[10];
    float* out = (float*)d_out;

    float *ln, *qkv, *pre, *x1, *mid, *lg, *wr;
    cudaGetSymbolAddress((void**)&ln,  g_ln);
    cudaGetSymbolAddress((void**)&qkv, g_qkv);
    cudaGetSymbolAddress((void**)&pre, g_pre);
    cudaGetSymbolAddress((void**)&x1,  g_x1);
    cudaGetSymbolAddress((void**)&mid, g_mid);
    cudaGetSymbolAddress((void**)&lg,  g_logits);
    cudaGetSymbolAddress((void**)&wr,  g_wr);

    const long long MM = (long long)D_MODEL * D_MODEL;   // 1M
    float* wqkv = wr;                 // wq | wk | wv contiguous
    float* wo   = wr + 3 * MM;
    float* wu   = wr + 4 * MM;
    float* wd   = wr + 8 * MM;
    float* q = qkv;
    float* k = qkv + (long long)MTOK * D_MODEL;
    float* v = qkv + 2 * (long long)MTOK * D_MODEL;

    // dynamic smem sizes + attribute (host-side, idempotent, capture-legal)
    constexpr int SMEM_NT = 4 * (128 * 20 + 128 * 20) * 4;   // 81920 B
    constexpr int SMEM_NN = 4 * (128 * 20 + 16 * 72) * 4;    // 59392 B
    cudaFuncSetAttribute(gemm_tf32<128,128,32,64,true,EPI_NONE,true>,
                         cudaFuncAttributeMaxDynamicSharedMemorySize, SMEM_NT);
    cudaFuncSetAttribute(gemm_tf32<128,128,32,64,true,EPI_NONE,false>,
                         cudaFuncAttributeMaxDynamicSharedMemorySize, SMEM_NT);
    cudaFuncSetAttribute(gemm_tf32<128,128,32,64,true,EPI_RES,false>,
                         cudaFuncAttributeMaxDynamicSharedMemorySize, SMEM_NT);
    cudaFuncSetAttribute(gemm_tf32<128,128,32,64,true,EPI_GELU,true>,
                         cudaFuncAttributeMaxDynamicSharedMemorySize, SMEM_NT);
    cudaFuncSetAttribute(gemm_tf32<128,64,32,32,false,EPI_NONE,true>,
                         cudaFuncAttributeMaxDynamicSharedMemorySize, SMEM_NN);

    const long long SS2  = (long long)SEQ * SEQ;
    const long long TOKD = (long long)SEQ * D_MODEL;

    // 0) round weights to tf32 (cheap; removes truncation bias in mma inputs)
    round_tf32_kernel<<<(int)(MM / 1024), 256>>>(Wq, wqkv);
    round_tf32_kernel<<<(int)(MM / 1024), 256>>>(Wk, wqkv + MM);
    round_tf32_kernel<<<(int)(MM / 1024), 256>>>(Wv, wqkv + 2 * MM);
    round_tf32_kernel<<<(int)(MM / 1024), 256>>>(Wo, wo);
    round_tf32_kernel<<<(int)(4 * MM / 1024), 256>>>(Wup, wu);
    round_tf32_kernel<<<(int)(4 * MM / 1024), 256>>>(Wdown, wd);

    // 1) LN1 (output rounded)
    ln_kernel<<<MTOK, 256>>>(x, ln, m1, s1);

    // 2) QKV = ln @ [Wq|Wk|Wv]^T  — one batched launch, z in {q,k,v}
    dim3 gqkv3(D_MODEL / 128, MTOK / 128, 3);
    gemm_tf32<128,128,32,64,true,EPI_NONE,true><<<gqkv3, 256, SMEM_NT>>>(
        ln, wqkv, qkv, nullptr, D_MODEL, D_MODEL, D_MODEL, D_MODEL,
        1,
        0, 0,                                 // A: same for all z
        MM, 0,                                // B: z-th weight matrix
        (long long)MTOK * D_MODEL, 0,         // C: z-th output block
        1.0f);

    // 3) logits[bh] = (Q_bh @ K_bh^T) / 8 (exact output; softmax rounds)
    dim3 glog(SEQ / 128, SEQ / 128, BATCH * NHEADS);
    gemm_tf32<128,128,32,64,true,EPI_NONE,false><<<glog, 256, SMEM_NT>>>(
        q, k, lg, nullptr, HDIM, D_MODEL, D_MODEL, SEQ,
        NHEADS,
        TOKD, (long long)HDIM,
        TOKD, (long long)HDIM,
        (long long)NHEADS * SS2, SS2,
        0.125f);

    // 4) causal softmax in place (output rounded)
    softmax_causal_kernel<<<BATCH * NHEADS * SEQ, 256>>>(lg);

    // 5) pre[bh] = P_bh @ V_bh (NN; output rounded)
    dim3 gpv(HDIM / 64, SEQ / 128, BATCH * NHEADS);
    gemm_tf32<128,64,32,32,false,EPI_NONE,true><<<gpv, 256, SMEM_NN>>>(
        lg, v, pre, nullptr, SEQ, SEQ, D_MODEL, D_MODEL,
        NHEADS,
        (long long)NHEADS * SS2, SS2,
        TOKD, (long long)HDIM,
        TOKD, (long long)HDIM,
        1.0f);

    // 6) x1 = x + pre @ Wo^T (exact)
    dim3 gproj(D_MODEL / 128, MTOK / 128, 1);
    gemm_tf32<128,128,32,64,true,EPI_RES,false><<<gproj, 256, SMEM_NT>>>(
        pre, wo, x1, x, D_MODEL, D_MODEL, D_MODEL, D_MODEL,
        1, 0,0, 0,0, 0,0, 1.0f);

    // 7) LN2 (output rounded)
    ln_kernel<<<MTOK, 256>>>(x1, ln, m2, s2);

    // 8) mid = gelu(ln2 @ Wup^T) (output rounded)
    dim3 gup(DFF / 128, MTOK / 128, 1);
    gemm_tf32<128,128,32,64,true,EPI_GELU,true><<<gup, 256, SMEM_NT>>>(
        ln, wu, mid, nullptr, D_MODEL, D_MODEL, D_MODEL, DFF,
        1, 0,0, 0,0, 0,0, 1.0f);

    // 9) out = x1 + mid @ Wdown^T (exact)
    gemm_tf32<128,128,32,64,true,EPI_RES,false><<<gproj, 256, SMEM_NT>>>(
        mid, wd, out, x1, DFF, DFF, DFF, D_MODEL,
        1, 0,0, 0,0, 0,0, 1.0f);
}

// round 9
// speedup vs baseline: 1.6785x; 1.2967x over previous
#include <cuda_runtime.h>
#include <math.h>

// ---------------------------------------------------------------------------
// Problem constants
// ---------------------------------------------------------------------------
#define D_MODEL 1024
#define SEQ     2048
#define BATCH   2
#define NHEADS  16
#define HDIM    64
#define MTOK    (BATCH*SEQ)        // 4096 token rows
#define DFF     (4*D_MODEL)        // 4096

// ---------------------------------------------------------------------------
// Scratch (device globals: allocation-free contract)
// ---------------------------------------------------------------------------
__device__ float g_ln  [MTOK*D_MODEL];
__device__ float g_qkv [3*MTOK*D_MODEL];          // q | k | v contiguous
__device__ float g_pre [MTOK*D_MODEL];
__device__ float g_x1  [MTOK*D_MODEL];
__device__ float g_mid [MTOK*DFF];
// tf32-rounded weights: Wq,Wk,Wv (contiguous), Wo, Wup, Wdown
__device__ float g_wr[4*D_MODEL*D_MODEL + 2*(long long)DFF*D_MODEL];

// ---------------------------------------------------------------------------
// Helpers
// ---------------------------------------------------------------------------
__device__ __forceinline__ unsigned f2tf(float x) {
    unsigned u; asm("cvt.rna.tf32.f32 %0, %1;" : "=r"(u) : "f"(x)); return u;
}
__device__ __forceinline__ float rnd_tf32(float x) { return __uint_as_float(f2tf(x)); }
__device__ __forceinline__ float geluf(float x) {
    return 0.5f * x * (1.0f + erff(x * 0.7071067811865475f));
}
__device__ __forceinline__ void mma8(float* d, const unsigned* a, const unsigned* b) {
    asm volatile(
        "mma.sync.aligned.m16n8k8.row.col.f32.tf32.tf32.f32 "
        "{%0,%1,%2,%3}, {%4,%5,%6,%7}, {%8,%9}, {%0,%1,%2,%3};\n"
        : "+f"(d[0]), "+f"(d[1]), "+f"(d[2]), "+f"(d[3])
        : "r"(a[0]), "r"(a[1]), "r"(a[2]), "r"(a[3]), "r"(b[0]), "r"(b[1]));
}
__device__ __forceinline__ void ldsm4(unsigned& r0, unsigned& r1, unsigned& r2,
                                      unsigned& r3, unsigned a) {
    asm volatile("ldmatrix.sync.aligned.m8n8.x4.shared.b16 {%0,%1,%2,%3}, [%4];"
                 : "=r"(r0), "=r"(r1), "=r"(r2), "=r"(r3) : "r"(a));
}
__device__ __forceinline__ void cpasync16(unsigned dst, const float* src) {
    asm volatile("cp.async.cg.shared.global [%0], [%1], 16;\n"
                 :: "r"(dst), "l"(src) : "memory");
}
__device__ __forceinline__ float warpsum(float x) {
    #pragma unroll
    for (int o = 16; o; o >>= 1) x += __shfl_xor_sync(0xffffffffu, x, o);
    return x;
}

#define EPI_NONE 0
#define EPI_RES  1
#define EPI_GELU 2

// ---------------------------------------------------------------------------
// tf32 GEMM (NT):  C = alpha * A(MxK) * B^T [+ Res]   B is [N][K] row-major.
// Inputs already tf32-rounded. cp.async 4-stage pipeline + ldmatrix.x4.
// ---------------------------------------------------------------------------
template<int BM, int BN, int WM, int WN, bool BNT, int EPI, bool RND>
__global__ void __launch_bounds__(256, 2)
gemm_tf32(const float* __restrict__ A, const float* __restrict__ B,
          float* __restrict__ C, const float* __restrict__ R,
          int K, int lda, int ldb, int ldc, int ZH,
          long long sA1, long long sA2, long long sB1, long long sB2,
          long long sC1, long long sC2, float alpha)
{
    constexpr int BK   = 16;
    constexpr int AST  = BK + 4;           // 20 words
    constexpr int BSTN = BN + 8;
    constexpr int MT   = WM / 16;
    constexpr int NTL  = WN / 8;
    constexpr int SA_SZ = BM * AST;
    constexpr int SB_SZ = BNT ? BN * AST : BK * BSTN;
    constexpr int STAGE_SZ = SA_SZ + SB_SZ;
    constexpr int STAGES = 4;
    constexpr int AVEC = BM * BK / (4 * 256);
    constexpr int BVEC = (BNT ? BN * BK : BK * BN) / (4 * 256);

    extern __shared__ float smem[];
    const unsigned smem_base = (unsigned)__cvta_generic_to_shared(smem);

    const int z = blockIdx.z;
    const long long zb = z / ZH, zh = z % ZH;
    A += zb * sA1 + zh * sA2;
    B += zb * sB1 + zh * sB2;
    C += zb * sC1 + zh * sC2;
    if (EPI == EPI_RES) R += zb * sC1 + zh * sC2;

    const int tid = threadIdx.x, lane = tid & 31, wid = tid >> 5;
    constexpr int WROWS = BM / WM;
    const int wm = wid % WROWS, wn = wid / WROWS;
    const int bm0 = blockIdx.y * BM, bn0 = blockIdx.x * BN;
    const int nkt = K / BK;

    auto issue = [&](int kt, int st) {
        const unsigned sa = smem_base + st * (STAGE_SZ * 4);
        #pragma unroll
        for (int i = 0; i < AVEC; i++) {
            int f = tid + i * 256; int r = f >> 2, c = f & 3;
            cpasync16(sa + (r * AST + 4 * c) * 4,
                      A + (long long)(bm0 + r) * lda + kt * BK + 4 * c);
        }
        const unsigned sb = sa + SA_SZ * 4;
        #pragma unroll
        for (int i = 0; i < BVEC; i++) {
            int f = tid + i * 256;
            if (BNT) {
                int r = f >> 2, c = f & 3;
                cpasync16(sb + (r * AST + 4 * c) * 4,
                          B + (long long)(bn0 + r) * ldb + kt * BK + 4 * c);
            } else {
                int r = f / (BN / 4), c = f % (BN / 4);
                cpasync16(sb + (r * BSTN + 4 * c) * 4,
                          B + (long long)(kt * BK + r) * ldb + bn0 + 4 * c);
            }
        }
    };

    #pragma unroll
    for (int s = 0; s < STAGES - 1; s++) {
        issue(s, s);
        asm volatile("cp.async.commit_group;\n" ::: "memory");
    }

    const int r8 = lane & 7, q = lane >> 3;
    const int g = lane >> 2, t4 = lane & 3;
    unsigned aoff[MT];
    #pragma unroll
    for (int mt = 0; mt < MT; mt++)
        aoff[mt] = ((wm * WM + mt * 16 + (q & 1) * 8 + r8) * AST + (q >> 1) * 4) * 4;
    unsigned boff[(NTL + 1) / 2];
    if (BNT) {
        #pragma unroll
        for (int p = 0; p < NTL / 2; p++)
            boff[p] = SA_SZ * 4 +
                ((wn * WN + p * 16 + (q >> 1) * 8 + r8) * AST + (q & 1) * 4) * 4;
    }

    float acc[MT][NTL][4];
    #pragma unroll
    for (int a = 0; a < MT; a++)
        #pragma unroll
        for (int b = 0; b < NTL; b++)
            #pragma unroll
            for (int c = 0; c < 4; c++) acc[a][b][c] = 0.f;

    for (int kt = 0; kt < nkt; kt++) {
        asm volatile("cp.async.wait_group %0;\n" :: "n"(STAGES - 2) : "memory");
        __syncthreads();
        if (kt + STAGES - 1 < nkt) issue(kt + STAGES - 1, (kt + STAGES - 1) % STAGES);
        asm volatile("cp.async.commit_group;\n" ::: "memory");

        const int st = kt % STAGES;
        const unsigned sa = smem_base + st * (STAGE_SZ * 4);
        const unsigned* sbw = reinterpret_cast<const unsigned*>(smem) +
                              st * STAGE_SZ + SA_SZ;

        #pragma unroll
        for (int kk = 0; kk < BK; kk += 8) {
            unsigned af[MT][4], bf[NTL][2];
            #pragma unroll
            for (int mt = 0; mt < MT; mt++)
                ldsm4(af[mt][0], af[mt][1], af[mt][2], af[mt][3],
                      sa + aoff[mt] + kk * 4);
            if (BNT) {
                #pragma unroll
                for (int p = 0; p < NTL / 2; p++)
                    ldsm4(bf[2 * p][0], bf[2 * p][1], bf[2 * p + 1][0], bf[2 * p + 1][1],
                          sa + boff[p] + kk * 4);
            } else {
                #pragma unroll
                for (int nt = 0; nt < NTL; nt++) {
                    int col = wn * WN + nt * 8 + g;
                    bf[nt][0] = sbw[(kk + t4) * BSTN + col];
                    bf[nt][1] = sbw[(kk + t4 + 4) * BSTN + col];
                }
            }
            #pragma unroll
            for (int mt = 0; mt < MT; mt++)
                #pragma unroll
                for (int nt = 0; nt < NTL; nt++)
                    mma8(acc[mt][nt], af[mt], bf[nt]);
        }
    }

    #pragma unroll
    for (int mt = 0; mt < MT; mt++) {
        #pragma unroll
        for (int nt = 0; nt < NTL; nt++) {
            int cm = bm0 + wm * WM + mt * 16 + g;
            int cn = bn0 + wn * WN + nt * 8 + 2 * t4;
            #pragma unroll
            for (int h = 0; h < 2; h++) {
                long long idx = (long long)(cm + 8 * h) * ldc + cn;
                float vx = alpha * acc[mt][nt][2 * h];
                float vy = alpha * acc[mt][nt][2 * h + 1];
                if (EPI == EPI_RES) {
                    float2 r2 = *reinterpret_cast<const float2*>(R + idx);
                    vx += r2.x; vy += r2.y;
                }
                if (EPI == EPI_GELU) { vx = geluf(vx); vy = geluf(vy); }
                if (RND) { vx = rnd_tf32(vx); vy = rnd_tf32(vy); }
                float2 o; o.x = vx; o.y = vy;
                *reinterpret_cast<float2*>(C + idx) = o;
            }
        }
    }
}

// ---------------------------------------------------------------------------
// Fused causal flash attention (tf32 mma).
// Grid (1, SEQ/128, BATCH*NHEADS). 256 threads, 8 warps; warp owns 16 q-rows.
// K: double-buffered cp.async, NT layout stride 68.
// V: cp.async into Vraw, transposed in smem to Vt (rows=hdim), stride 68.
// S in mma accumulators; online softmax; P via warp-private smem -> ldmatrix.
// ---------------------------------------------------------------------------
#define KST 68
#define KSZ (64*KST)                  // words per 64-row tile
#define OFF_VR (2*KSZ)
#define OFF_VT (3*KSZ)
#define OFF_P  (4*KSZ)
#define FLASH_SMEM ((4*KSZ + 8*16*KST)*4)   // 104448 bytes

__global__ void __launch_bounds__(256, 2)
flash_attn(const float* __restrict__ Qg, const float* __restrict__ Kg,
           const float* __restrict__ Vg, float* __restrict__ Og)
{
    extern __shared__ float sm[];
    const unsigned smb = (unsigned)__cvta_generic_to_shared(sm);

    const int tid = threadIdx.x, lane = tid & 31, wid = tid >> 5;
    const int g = lane >> 2, t4 = lane & 3;
    const int r8 = lane & 7, q2 = lane >> 3;
    const int y = blockIdx.y, bh = blockIdx.z;
    const int b = bh >> 4, h = bh & 15;
    const long long qtok0 = (long long)b * SEQ + y * 128;
    const long long ktok0 = (long long)b * SEQ;
    const int hoff = h * HDIM;
    const int nkv = 2 * (y + 1);

    // ---- Q fragments in registers, pre-scaled by 1/8 (exact for tf32) ----
    unsigned qa[8][4];
    {
        const float* qp = Qg + (qtok0 + wid * 16) * D_MODEL + hoff;
        #pragma unroll
        for (int j = 0; j < 8; j++) {
            qa[j][0] = __float_as_uint(qp[(g    ) * D_MODEL + j * 8 + t4    ] * 0.125f);
            qa[j][1] = __float_as_uint(qp[(g + 8) * D_MODEL + j * 8 + t4    ] * 0.125f);
            qa[j][2] = __float_as_uint(qp[(g    ) * D_MODEL + j * 8 + t4 + 4] * 0.125f);
            qa[j][3] = __float_as_uint(qp[(g + 8) * D_MODEL + j * 8 + t4 + 4] * 0.125f);
        }
    }

    float o[8][4];
    #pragma unroll
    for (int nt = 0; nt < 8; nt++)
        #pragma unroll
        for (int c = 0; c < 4; c++) o[nt][c] = 0.f;
    float mrow[2] = {-1e30f, -1e30f}, lrow[2] = {0.f, 0.f};

    auto issueK = [&](int t) {
        const unsigned dst = smb + ((t & 1) * KSZ) * 4;
        const float* src = Kg + (ktok0 + t * 64) * D_MODEL + hoff;
        #pragma unroll
        for (int i = 0; i < 4; i++) {
            int f = tid + i * 256; int r = f >> 4, c4 = f & 15;
            cpasync16(dst + (r * KST + 4 * c4) * 4, src + (long long)r * D_MODEL + 4 * c4);
        }
        asm volatile("cp.async.commit_group;\n" ::: "memory");
    };
    auto issueV = [&](int t) {
        const unsigned dst = smb + OFF_VR * 4;
        const float* src = Vg + (ktok0 + t * 64) * D_MODEL + hoff;
        #pragma unroll
        for (int i = 0; i < 4; i++) {
            int f = tid + i * 256; int r = f >> 4, c4 = f & 15;
            cpasync16(dst + (r * KST + 4 * c4) * 4, src + (long long)r * D_MODEL + 4 * c4);
        }
        asm volatile("cp.async.commit_group;\n" ::: "memory");
    };

    issueK(0); issueV(0);

    for (int t = 0; t < nkv; t++) {
        asm volatile("cp.async.wait_group 0;\n" ::: "memory");
        __syncthreads();                            // K(t), Vraw(t) visible to all
        if (t + 1 < nkv) issueK(t + 1);

        // ---- transpose Vraw -> Vt (rows = hdim) ----
        #pragma unroll
        for (int i = 0; i < 4; i++) {
            int c = tid + i * 256; int d = c & 63, kg = c >> 6;
            float e0 = sm[OFF_VR + (4 * kg + 0) * KST + d];
            float e1 = sm[OFF_VR + (4 * kg + 1) * KST + d];
            float e2 = sm[OFF_VR + (4 * kg + 2) * KST + d];
            float e3 = sm[OFF_VR + (4 * kg + 3) * KST + d];
            *reinterpret_cast<float4*>(&sm[OFF_VT + d * KST + 4 * kg]) =
                make_float4(e0, e1, e2, e3);
        }

        // ---- S = (Q/8) @ K^T ----
        float s[8][4];
        #pragma unroll
        for (int nt = 0; nt < 8; nt++)
            #pragma unroll
            for (int c = 0; c < 4; c++) s[nt][c] = 0.f;

        const unsigned kb = smb + ((t & 1) * KSZ) * 4;
        #pragma unroll
        for (int j = 0; j < 8; j++) {
            #pragma unroll
            for (int p = 0; p < 4; p++) {
                unsigned b0, b1, b2, b3;
                ldsm4(b0, b1, b2, b3,
                      kb + ((p * 16 + (q2 >> 1) * 8 + r8) * KST + (q2 & 1) * 4 + j * 8) * 4);
                unsigned bf0[2] = {b0, b1}, bf1[2] = {b2, b3};
                mma8(s[2 * p],     qa[j], bf0);
                mma8(s[2 * p + 1], qa[j], bf1);
            }
        }
        __syncthreads();                            // Vt complete; Vraw reads done
        if (t + 1 < nkv) issueV(t + 1);

        // ---- causal mask (only last two tiles can touch the diagonal) ----
        if (t >= 2 * y) {
            const int qb = y * 128 + wid * 16 + g;
            const int kbc = t * 64 + 2 * t4;
            #pragma unroll
            for (int nt = 0; nt < 8; nt++) {
                #pragma unroll
                for (int v = 0; v < 2; v++) {
                    int kc = kbc + nt * 8 + v;
                    if (kc > qb)     s[nt][v]     = -1e30f;
                    if (kc > qb + 8) s[nt][2 + v] = -1e30f;
                }
            }
        }

        // ---- online softmax (rows g and g+8, quad-lane reductions) ----
        #pragma unroll
        for (int hh = 0; hh < 2; hh++) {
            float rmax = -1e30f;
            #pragma unroll
            for (int nt = 0; nt < 8; nt++)
                rmax = fmaxf(rmax, fmaxf(s[nt][2 * hh], s[nt][2 * hh + 1]));
            rmax = fmaxf(rmax, __shfl_xor_sync(0xffffffffu, rmax, 1));
            rmax = fmaxf(rmax, __shfl_xor_sync(0xffffffffu, rmax, 2));
            float newm = fmaxf(mrow[hh], rmax);
            float alpha = __expf(mrow[hh] - newm);
            mrow[hh] = newm;
            float rsum = 0.f;
            #pragma unroll
            for (int nt = 0; nt < 8; nt++) {
                float p0 = __expf(s[nt][2 * hh]     - newm);
                float p1 = __expf(s[nt][2 * hh + 1] - newm);
                s[nt][2 * hh] = p0; s[nt][2 * hh + 1] = p1;
                rsum += p0 + p1;
                o[nt][2 * hh]     *= alpha;
                o[nt][2 * hh + 1] *= alpha;
            }
            rsum += __shfl_xor_sync(0xffffffffu, rsum, 1);
            rsum += __shfl_xor_sync(0xffffffffu, rsum, 2);
            lrow[hh] = lrow[hh] * alpha + rsum;
        }

        // ---- P to warp-private smem (tf32-rounded), then O += P @ V ----
        {
            float* pw = &sm[OFF_P + wid * 16 * KST];
            #pragma unroll
            for (int nt = 0; nt < 8; nt++) {
                float2 p0; p0.x = rnd_tf32(s[nt][0]); p0.y = rnd_tf32(s[nt][1]);
                float2 p1; p1.x = rnd_tf32(s[nt][2]); p1.y = rnd_tf32(s[nt][3]);
                *reinterpret_cast<float2*>(&pw[ g      * KST + nt * 8 + 2 * t4]) = p0;
                *reinterpret_cast<float2*>(&pw[(g + 8) * KST + nt * 8 + 2 * t4]) = p1;
            }
        }
        __syncwarp();
        {
            const unsigned pb  = smb + (OFF_P + wid * 16 * KST) * 4;
            const unsigned vtb = smb + OFF_VT * 4;
            #pragma unroll
            for (int j = 0; j < 8; j++) {           // k = key dim, 8 per step
                unsigned af[4];
                ldsm4(af[0], af[1], af[2], af[3],
                      pb + (((q2 & 1) * 8 + r8) * KST + (q2 >> 1) * 4 + j * 8) * 4);
                #pragma unroll
                for (int p = 0; p < 4; p++) {
                    unsigned b0, b1, b2, b3;
                    ldsm4(b0, b1, b2, b3,
                          vtb + ((p * 16 + (q2 >> 1) * 8 + r8) * KST + (q2 & 1) * 4 + j * 8) * 4);
                    unsigned bf0[2] = {b0, b1}, bf1[2] = {b2, b3};
                    mma8(o[2 * p],     af, bf0);
                    mma8(o[2 * p + 1], af, bf1);
                }
            }
        }
    }

    // ---- normalize + write back (tf32-rounded: feeds Wo GEMM) ----
    #pragma unroll
    for (int hh = 0; hh < 2; hh++) {
        float inv = 1.0f / lrow[hh];
        long long tok = qtok0 + wid * 16 + g + 8 * hh;
        float* op = Og + tok * D_MODEL + hoff;
        #pragma unroll
        for (int nt = 0; nt < 8; nt++) {
            float2 w;
            w.x = rnd_tf32(o[nt][2 * hh]     * inv);
            w.y = rnd_tf32(o[nt][2 * hh + 1] * inv);
            *reinterpret_cast<float2*>(&op[nt * 8 + 2 * t4]) = w;
        }
    }
}

// ---------------------------------------------------------------------------
// Single-launch tf32 rounding of all weights into g_wr (segment dispatch).
// Segments (float4 units): Wq,Wk,Wv,Wo = 262144 each; Wup,Wdown = 1048576.
// ---------------------------------------------------------------------------
__global__ void __launch_bounds__(256)
round_all_kernel(const float* __restrict__ Wq, const float* __restrict__ Wk,
                 const float* __restrict__ Wv, const float* __restrict__ Wo,
                 const float* __restrict__ Wup, const float* __restrict__ Wdown,
                 float* __restrict__ dst)
{
    long long i = (long long)blockIdx.x * 256 + threadIdx.x;   // float4 index
    long long f = i;
    const float* s;
    if      (f < 262144)  { s = Wq; }
    else if (f < 524288)  { s = Wk;    f -= 262144; }
    else if (f < 786432)  { s = Wv;    f -= 524288; }
    else if (f < 1048576) { s = Wo;    f -= 786432; }
    else if (f < 2097152) { s = Wup;   f -= 1048576; }
    else                  { s = Wdown; f -= 2097152; }
    float4 v = reinterpret_cast<const float4*>(s)[f];
    v.x = rnd_tf32(v.x); v.y = rnd_tf32(v.y);
    v.z = rnd_tf32(v.z); v.w = rnd_tf32(v.w);
    reinterpret_cast<float4*>(dst)[i] = v;
}

// ---------------------------------------------------------------------------
// LayerNorm (torch-style unbiased var). Output tf32-rounded.
// ---------------------------------------------------------------------------
__global__ void __launch_bounds__(256)
ln_kernel(const float* __restrict__ X, float* __restrict__ Y,
          const float* __restrict__ MS, const float* __restrict__ SS)
{
    __shared__ float shs[8], shq[8];
    const int tid = threadIdx.x;
    const long long base = (long long)blockIdx.x * D_MODEL;
    float4 v = reinterpret_cast<const float4*>(X + base)[tid];
    float s = v.x + v.y + v.z + v.w;
    float qq = v.x * v.x + v.y * v.y + v.z * v.z + v.w * v.w;
    s = warpsum(s); qq = warpsum(qq);
    if ((tid & 31) == 0) { shs[tid >> 5] = s; shq[tid >> 5] = qq; }
    __syncthreads();
    float ts = 0.f, tq = 0.f;
    #pragma unroll
    for (int i = 0; i < 8; i++) { ts += shs[i]; tq += shq[i]; }
    float mean = ts * (1.0f / D_MODEL);
    float var  = (tq - (float)D_MODEL * mean * mean) * (1.0f / (D_MODEL - 1));
    float rstd = rsqrtf(var + 1e-9f);
    float4 ms = reinterpret_cast<const float4*>(MS)[tid];
    float4 ss = reinterpret_cast<const float4*>(SS)[tid];
    float4 o2;
    o2.x = rnd_tf32((v.x - mean) * rstd * ss.x + ms.x);
    o2.y = rnd_tf32((v.y - mean) * rstd * ss.y + ms.y);
    o2.z = rnd_tf32((v.z - mean) * rstd * ss.z + ms.z);
    o2.w = rnd_tf32((v.w - mean) * rstd * ss.w + ms.w);
    reinterpret_cast<float4*>(Y + base)[tid] = o2;
}

// ---------------------------------------------------------------------------
// kernel_launch
// ---------------------------------------------------------------------------
extern "C" void kernel_launch(void* const* d_in, const int* in_sizes, int n_in,
                              void* d_out, int out_size)
{
    const float* x     = (const float*)d_in[0];
    const float* Wq    = (const float*)d_in[1];
    const float* Wk    = (const float*)d_in[2];
    const float* Wv    = (const float*)d_in[3];
    const float* Wo    = (const float*)d_in[4];
    const float* Wup   = (const float*)d_in[5];
    const float* Wdown = (const float*)d_in[6];
    const float* m1    = (const float*)d_in[7];
    const float* s1    = (const float*)d_in[8];
    const float* m2    = (const float*)d_in[9];
    const float* s2    = (const float*)d_in[10];
    float* out = (float*)d_out;

    float *ln, *qkv, *pre, *x1, *mid, *wr;
    cudaGetSymbolAddress((void**)&ln,  g_ln);
    cudaGetSymbolAddress((void**)&qkv, g_qkv);
    cudaGetSymbolAddress((void**)&pre, g_pre);
    cudaGetSymbolAddress((void**)&x1,  g_x1);
    cudaGetSymbolAddress((void**)&mid, g_mid);
    cudaGetSymbolAddress((void**)&wr,  g_wr);

    const long long MM = (long long)D_MODEL * D_MODEL;   // 1M
    float* wqkv = wr;
    float* wo   = wr + 3 * MM;
    float* wu   = wr + 4 * MM;
    float* wd   = wr + 8 * MM;
    float* q = qkv;
    float* k = qkv + (long long)MTOK * D_MODEL;
    float* v = qkv + 2 * (long long)MTOK * D_MODEL;

    constexpr int SMEM_NT = 4 * (128 * 20 + 128 * 20) * 4;   // 81920 B
    cudaFuncSetAttribute(gemm_tf32<128,128,32,64,true,EPI_NONE,true>,
                         cudaFuncAttributeMaxDynamicSharedMemorySize, SMEM_NT);
    cudaFuncSetAttribute(gemm_tf32<128,128,32,64,true,EPI_RES,false>,
                         cudaFuncAttributeMaxDynamicSharedMemorySize, SMEM_NT);
    cudaFuncSetAttribute(gemm_tf32<128,128,32,64,true,EPI_GELU,true>,
                         cudaFuncAttributeMaxDynamicSharedMemorySize, SMEM_NT);
    cudaFuncSetAttribute(flash_attn,
                         cudaFuncAttributeMaxDynamicSharedMemorySize, FLASH_SMEM);

    // 0) round all weights to tf32 (one launch)
    round_all_kernel<<<12288, 256>>>(Wq, Wk, Wv, Wo, Wup, Wdown, wr);

    // 1) LN1
    ln_kernel<<<MTOK, 256>>>(x, ln, m1, s1);

    // 2) QKV = ln @ [Wq|Wk|Wv]^T (one batched launch)
    dim3 gqkv3(D_MODEL / 128, MTOK / 128, 3);
    gemm_tf32<128,128,32,64,true,EPI_NONE,true><<<gqkv3, 256, SMEM_NT>>>(
        ln, wqkv, qkv, nullptr, D_MODEL, D_MODEL, D_MODEL, D_MODEL,
        1, 0, 0, MM, 0, (long long)MTOK * D_MODEL, 0, 1.0f);

    // 3) fused causal attention -> pre
    dim3 gfa(1, SEQ / 128, BATCH * NHEADS);
    flash_attn<<<gfa, 256, FLASH_SMEM>>>(q, k, v, pre);

    // 4) x1 = x + pre @ Wo^T
    dim3 gproj(D_MODEL / 128, MTOK / 128, 1);
    gemm_tf32<128,128,32,64,true,EPI_RES,false><<<gproj, 256, SMEM_NT>>>(
        pre, wo, x1, x, D_MODEL, D_MODEL, D_MODEL, D_MODEL,
        1, 0,0, 0,0, 0,0, 1.0f);

    // 5) LN2
    ln_kernel<<<MTOK, 256>>>(x1, ln, m2, s2);

    // 6) mid = gelu(ln2 @ Wup^T)
    dim3 gup(DFF / 128, MTOK / 128, 1);
    gemm_tf32<128,128,32,64,true,EPI_GELU,true><<<gup, 256, SMEM_NT>>>(
        ln, wu, mid, nullptr, D_MODEL, D_MODEL, D_MODEL, DFF,
        1, 0,0, 0,0, 0,0, 1.0f);

    // 7) out = x1 + mid @ Wdown^T
    gemm_tf32<128,128,32,64,true,EPI_RES,false><<<gproj, 256, SMEM_NT>>>(
        mid, wd, out, x1, DFF, DFF, DFF, D_MODEL,
        1, 0,0, 0,0, 0,0, 1.0f);
}

// round 10
// speedup vs baseline: 1.8332x; 1.0922x over previous
#include <cuda_runtime.h>
#include <math.h>

// ---------------------------------------------------------------------------
// Problem constants
// ---------------------------------------------------------------------------
#define D_MODEL 1024
#define SEQ     2048
#define BATCH   2
#define NHEADS  16
#define HDIM    64
#define MTOK    (BATCH*SEQ)        // 4096 token rows
#define DFF     (4*D_MODEL)        // 4096

// ---------------------------------------------------------------------------
// Scratch (device globals: allocation-free contract)
// ---------------------------------------------------------------------------
__device__ float g_ln  [MTOK*D_MODEL];
__device__ float g_qkv [3*MTOK*D_MODEL];          // q | k | v contiguous
__device__ float g_vt  [(long long)BATCH*NHEADS*HDIM*SEQ];  // V transposed [bh][d][s]
__device__ float g_pre [MTOK*D_MODEL];
__device__ float g_x1  [MTOK*D_MODEL];
__device__ float g_mid [MTOK*DFF];
// tf32-rounded weights: Wq,Wk,Wv (contiguous), Wo, Wup, Wdown
__device__ float g_wr[4*D_MODEL*D_MODEL + 2*(long long)DFF*D_MODEL];

// ---------------------------------------------------------------------------
// Helpers
// ---------------------------------------------------------------------------
__device__ __forceinline__ unsigned f2tf(float x) {
    unsigned u; asm("cvt.rna.tf32.f32 %0, %1;" : "=r"(u) : "f"(x)); return u;
}
__device__ __forceinline__ float rnd_tf32(float x) { return __uint_as_float(f2tf(x)); }
__device__ __forceinline__ float geluf(float x) {
    return 0.5f * x * (1.0f + erff(x * 0.7071067811865475f));
}
__device__ __forceinline__ void mma8(float* d, const unsigned* a, const unsigned* b) {
    asm volatile(
        "mma.sync.aligned.m16n8k8.row.col.f32.tf32.tf32.f32 "
        "{%0,%1,%2,%3}, {%4,%5,%6,%7}, {%8,%9}, {%0,%1,%2,%3};\n"
        : "+f"(d[0]), "+f"(d[1]), "+f"(d[2]), "+f"(d[3])
        : "r"(a[0]), "r"(a[1]), "r"(a[2]), "r"(a[3]), "r"(b[0]), "r"(b[1]));
}
__device__ __forceinline__ void ldsm4(unsigned& r0, unsigned& r1, unsigned& r2,
                                      unsigned& r3, unsigned a) {
    asm volatile("ldmatrix.sync.aligned.m8n8.x4.shared.b16 {%0,%1,%2,%3}, [%4];"
                 : "=r"(r0), "=r"(r1), "=r"(r2), "=r"(r3) : "r"(a));
}
__device__ __forceinline__ void cpasync16(unsigned dst, const float* src) {
    asm volatile("cp.async.cg.shared.global [%0], [%1], 16;\n"
                 :: "r"(dst), "l"(src) : "memory");
}
__device__ __forceinline__ float warpsum(float x) {
    #pragma unroll
    for (int o = 16; o; o >>= 1) x += __shfl_xor_sync(0xffffffffu, x, o);
    return x;
}

#define EPI_NONE 0
#define EPI_RES  1
#define EPI_GELU 2

// ---------------------------------------------------------------------------
// tf32 GEMM (NT):  C = alpha * A(MxK) * B^T [+ Res]   B is [N][K] row-major.
// Inputs already tf32-rounded. cp.async 5-stage pipeline + ldmatrix.x4.
// ---------------------------------------------------------------------------
template<int BM, int BN, int WM, int WN, bool BNT, int EPI, bool RND>
__global__ void __launch_bounds__(256, 2)
gemm_tf32(const float* __restrict__ A, const float* __restrict__ B,
          float* __restrict__ C, const float* __restrict__ R,
          int K, int lda, int ldb, int ldc, int ZH,
          long long sA1, long long sA2, long long sB1, long long sB2,
          long long sC1, long long sC2, float alpha)
{
    constexpr int BK   = 16;
    constexpr int AST  = BK + 4;           // 20 words
    constexpr int BSTN = BN + 8;
    constexpr int MT   = WM / 16;
    constexpr int NTL  = WN / 8;
    constexpr int SA_SZ = BM * AST;
    constexpr int SB_SZ = BNT ? BN * AST : BK * BSTN;
    constexpr int STAGE_SZ = SA_SZ + SB_SZ;
    constexpr int STAGES = 5;
    constexpr int AVEC = BM * BK / (4 * 256);
    constexpr int BVEC = (BNT ? BN * BK : BK * BN) / (4 * 256);

    extern __shared__ float smem[];
    const unsigned smem_base = (unsigned)__cvta_generic_to_shared(smem);

    const int z = blockIdx.z;
    const long long zb = z / ZH, zh = z % ZH;
    A += zb * sA1 + zh * sA2;
    B += zb * sB1 + zh * sB2;
    C += zb * sC1 + zh * sC2;
    if (EPI == EPI_RES) R += zb * sC1 + zh * sC2;

    const int tid = threadIdx.x, lane = tid & 31, wid = tid >> 5;
    constexpr int WROWS = BM / WM;
    const int wm = wid % WROWS, wn = wid / WROWS;
    const int bm0 = blockIdx.y * BM, bn0 = blockIdx.x * BN;
    const int nkt = K / BK;

    auto issue = [&](int kt, int st) {
        const unsigned sa = smem_base + st * (STAGE_SZ * 4);
        #pragma unroll
        for (int i = 0; i < AVEC; i++) {
            int f = tid + i * 256; int r = f >> 2, c = f & 3;
            cpasync16(sa + (r * AST + 4 * c) * 4,
                      A + (long long)(bm0 + r) * lda + kt * BK + 4 * c);
        }
        const unsigned sb = sa + SA_SZ * 4;
        #pragma unroll
        for (int i = 0; i < BVEC; i++) {
            int f = tid + i * 256;
            if (BNT) {
                int r = f >> 2, c = f & 3;
                cpasync16(sb + (r * AST + 4 * c) * 4,
                          B + (long long)(bn0 + r) * ldb + kt * BK + 4 * c);
            } else {
                int r = f / (BN / 4), c = f % (BN / 4);
                cpasync16(sb + (r * BSTN + 4 * c) * 4,
                          B + (long long)(kt * BK + r) * ldb + bn0 + 4 * c);
            }
        }
    };

    #pragma unroll
    for (int s = 0; s < STAGES - 1; s++) {
        issue(s, s);                      // nkt >= 4 for all instantiations
        asm volatile("cp.async.commit_group;\n" ::: "memory");
    }

    const int r8 = lane & 7, q = lane >> 3;
    const int g = lane >> 2, t4 = lane & 3;
    unsigned aoff[MT];
    #pragma unroll
    for (int mt = 0; mt < MT; mt++)
        aoff[mt] = ((wm * WM + mt * 16 + (q & 1) * 8 + r8) * AST + (q >> 1) * 4) * 4;
    unsigned boff[(NTL + 1) / 2];
    if (BNT) {
        #pragma unroll
        for (int p = 0; p < NTL / 2; p++)
            boff[p] = SA_SZ * 4 +
                ((wn * WN + p * 16 + (q >> 1) * 8 + r8) * AST + (q & 1) * 4) * 4;
    }

    float acc[MT][NTL][4];
    #pragma unroll
    for (int a = 0; a < MT; a++)
        #pragma unroll
        for (int b = 0; b < NTL; b++)
            #pragma unroll
            for (int c = 0; c < 4; c++) acc[a][b][c] = 0.f;

    for (int kt = 0; kt < nkt; kt++) {
        asm volatile("cp.async.wait_group %0;\n" :: "n"(STAGES - 2) : "memory");
        __syncthreads();
        if (kt + STAGES - 1 < nkt) issue(kt + STAGES - 1, (kt + STAGES - 1) % STAGES);
        asm volatile("cp.async.commit_group;\n" ::: "memory");

        const int st = kt % STAGES;
        const unsigned sa = smem_base + st * (STAGE_SZ * 4);
        const unsigned* sbw = reinterpret_cast<const unsigned*>(smem) +
                              st * STAGE_SZ + SA_SZ;

        #pragma unroll
        for (int kk = 0; kk < BK; kk += 8) {
            unsigned af[MT][4], bf[NTL][2];
            #pragma unroll
            for (int mt = 0; mt < MT; mt++)
                ldsm4(af[mt][0], af[mt][1], af[mt][2], af[mt][3],
                      sa + aoff[mt] + kk * 4);
            if (BNT) {
                #pragma unroll
                for (int p = 0; p < NTL / 2; p++)
                    ldsm4(bf[2 * p][0], bf[2 * p][1], bf[2 * p + 1][0], bf[2 * p + 1][1],
                          sa + boff[p] + kk * 4);
            } else {
                #pragma unroll
                for (int nt = 0; nt < NTL; nt++) {
                    int col = wn * WN + nt * 8 + g;
                    bf[nt][0] = sbw[(kk + t4) * BSTN + col];
                    bf[nt][1] = sbw[(kk + t4 + 4) * BSTN + col];
                }
            }
            #pragma unroll
            for (int mt = 0; mt < MT; mt++)
                #pragma unroll
                for (int nt = 0; nt < NTL; nt++)
                    mma8(acc[mt][nt], af[mt], bf[nt]);
        }
    }

    #pragma unroll
    for (int mt = 0; mt < MT; mt++) {
        #pragma unroll
        for (int nt = 0; nt < NTL; nt++) {
            int cm = bm0 + wm * WM + mt * 16 + g;
            int cn = bn0 + wn * WN + nt * 8 + 2 * t4;
            #pragma unroll
            for (int h = 0; h < 2; h++) {
                long long idx = (long long)(cm + 8 * h) * ldc + cn;
                float vx = alpha * acc[mt][nt][2 * h];
                float vy = alpha * acc[mt][nt][2 * h + 1];
                if (EPI == EPI_RES) {
                    float2 r2 = *reinterpret_cast<const float2*>(R + idx);
                    vx += r2.x; vy += r2.y;
                }
                if (EPI == EPI_GELU) { vx = geluf(vx); vy = geluf(vy); }
                if (RND) { vx = rnd_tf32(vx); vy = rnd_tf32(vy); }
                float2 o; o.x = vx; o.y = vy;
                *reinterpret_cast<float2*>(C + idx) = o;
            }
        }
    }
}

// ---------------------------------------------------------------------------
// V transpose: v[b][s][h*64+d] -> vt[bh][d][s].  64x64 smem tiles, coalesced.
// ---------------------------------------------------------------------------
__global__ void __launch_bounds__(256)
transpose_v(const float* __restrict__ V, float* __restrict__ Vt)
{
    __shared__ float t[64][65];
    const int tid = threadIdx.x;
    const int bh = blockIdx.y, b = bh >> 4, h = bh & 15;
    const int s0 = blockIdx.x * 64;
    const float* src = V + ((long long)b * SEQ + s0) * D_MODEL + h * HDIM;
    #pragma unroll
    for (int i = 0; i < 4; i++) {
        int f = tid + i * 256; int r = f >> 4, c4 = f & 15;   // r=token, c4=d/4
        float4 v4 = *reinterpret_cast<const float4*>(src + (long long)r * D_MODEL + 4 * c4);
        t[r][4 * c4 + 0] = v4.x; t[r][4 * c4 + 1] = v4.y;
        t[r][4 * c4 + 2] = v4.z; t[r][4 * c4 + 3] = v4.w;
    }
    __syncthreads();
    float* dst = Vt + (long long)bh * HDIM * SEQ + s0;
    #pragma unroll
    for (int i = 0; i < 4; i++) {
        int f = tid + i * 256; int d = f >> 4, s4 = f & 15;   // d=row, s4=s/4
        float4 o;
        o.x = t[4 * s4 + 0][d]; o.y = t[4 * s4 + 1][d];
        o.z = t[4 * s4 + 2][d]; o.w = t[4 * s4 + 3][d];
        *reinterpret_cast<float4*>(dst + (long long)d * SEQ + 4 * s4) = o;
    }
}

// ---------------------------------------------------------------------------
// Fused causal flash attention (tf32 mma), v2.
// Grid (512): bx -> y = 15 - bx/32 (heavy tiles first), bh = bx%32.
// K and Vt both double-buffered via cp.async; one __syncthreads per k-tile.
// ---------------------------------------------------------------------------
#define KST 68
#define KSZ (64*KST)                  // words per 64-row tile
#define OFF_P  (4*KSZ)
#define FLASH_SMEM ((4*KSZ + 8*16*KST)*4)   // 104448 bytes

__global__ void __launch_bounds__(256, 2)
flash_attn(const float* __restrict__ Qg, const float* __restrict__ Kg,
           const float* __restrict__ Vtg, float* __restrict__ Og)
{
    extern __shared__ float sm[];
    const unsigned smb = (unsigned)__cvta_generic_to_shared(sm);

    const int tid = threadIdx.x, lane = tid & 31, wid = tid >> 5;
    const int g = lane >> 2, t4 = lane & 3;
    const int r8 = lane & 7, q2 = lane >> 3;
    const int bx = blockIdx.x;
    const int y = (SEQ / 128 - 1) - (bx >> 5);     // heavy first
    const int bh = bx & 31;
    const int b = bh >> 4, h = bh & 15;
    const long long qtok0 = (long long)b * SEQ + y * 128;
    const long long ktok0 = (long long)b * SEQ;
    const int hoff = h * HDIM;
    const int nkv = 2 * (y + 1);
    const float* vtb_g = Vtg + (long long)bh * HDIM * SEQ;

    // ---- Q fragments in registers, pre-scaled by 1/8 (exact for tf32) ----
    unsigned qa[8][4];
    {
        const float* qp = Qg + (qtok0 + wid * 16) * D_MODEL + hoff;
        #pragma unroll
        for (int j = 0; j < 8; j++) {
            qa[j][0] = __float_as_uint(qp[(g    ) * D_MODEL + j * 8 + t4    ] * 0.125f);
            qa[j][1] = __float_as_uint(qp[(g + 8) * D_MODEL + j * 8 + t4    ] * 0.125f);
            qa[j][2] = __float_as_uint(qp[(g    ) * D_MODEL + j * 8 + t4 + 4] * 0.125f);
            qa[j][3] = __float_as_uint(qp[(g + 8) * D_MODEL + j * 8 + t4 + 4] * 0.125f);
        }
    }

    float o[8][4];
    #pragma unroll
    for (int nt = 0; nt < 8; nt++)
        #pragma unroll
        for (int c = 0; c < 4; c++) o[nt][c] = 0.f;
    float mrow[2] = {-1e30f, -1e30f}, lrow[2] = {0.f, 0.f};

    // K tiles (rows=key, cols=hdim) in buffers 0/1; Vt tiles (rows=d, cols=key)
    // in buffers 2/3. One commit per t.
    auto issueKV = [&](int t) {
        const unsigned kd = smb + ((t & 1) * KSZ) * 4;
        const float* ks = Kg + (ktok0 + t * 64) * D_MODEL + hoff;
        #pragma unroll
        for (int i = 0; i < 4; i++) {
            int f = tid + i * 256; int r = f >> 4, c4 = f & 15;
            cpasync16(kd + (r * KST + 4 * c4) * 4, ks + (long long)r * D_MODEL + 4 * c4);
        }
        const unsigned vd = smb + ((2 + (t & 1)) * KSZ) * 4;
        const float* vs = vtb_g + t * 64;
        #pragma unroll
        for (int i = 0; i < 4; i++) {
            int f = tid + i * 256; int r = f >> 4, c4 = f & 15;   // r = d
            cpasync16(vd + (r * KST + 4 * c4) * 4, vs + (long long)r * SEQ + 4 * c4);
        }
        asm volatile("cp.async.commit_group;\n" ::: "memory");
    };

    issueKV(0);

    for (int t = 0; t < nkv; t++) {
        asm volatile("cp.async.wait_group 0;\n" ::: "memory");
        __syncthreads();                      // K(t), Vt(t) visible; t-1 reads done
        if (t + 1 < nkv) issueKV(t + 1);

        // ---- S = (Q/8) @ K^T ----
        float s[8][4];
        #pragma unroll
        for (int nt = 0; nt < 8; nt++)
            #pragma unroll
            for (int c = 0; c < 4; c++) s[nt][c] = 0.f;

        const unsigned kb = smb + ((t & 1) * KSZ) * 4;
        #pragma unroll
        for (int j = 0; j < 8; j++) {
            #pragma unroll
            for (int p = 0; p < 4; p++) {
                unsigned b0, b1, b2, b3;
                ldsm4(b0, b1, b2, b3,
                      kb + ((p * 16 + (q2 >> 1) * 8 + r8) * KST + (q2 & 1) * 4 + j * 8) * 4);
                unsigned bf0[2] = {b0, b1}, bf1[2] = {b2, b3};
                mma8(s[2 * p],     qa[j], bf0);
                mma8(s[2 * p + 1], qa[j], bf1);
            }
        }

        // ---- causal mask (only the two diagonal tiles) ----
        if (t >= 2 * y) {
            const int qb = y * 128 + wid * 16 + g;
            const int kbc = t * 64 + 2 * t4;
            #pragma unroll
            for (int nt = 0; nt < 8; nt++) {
                #pragma unroll
                for (int v = 0; v < 2; v++) {
                    int kc = kbc + nt * 8 + v;
                    if (kc > qb)     s[nt][v]     = -1e30f;
                    if (kc > qb + 8) s[nt][2 + v] = -1e30f;
                }
            }
        }

        // ---- online softmax (rows g and g+8, quad-lane reductions) ----
        #pragma unroll
        for (int hh = 0; hh < 2; hh++) {
            float rmax = -1e30f;
            #pragma unroll
            for (int nt = 0; nt < 8; nt++)
                rmax = fmaxf(rmax, fmaxf(s[nt][2 * hh], s[nt][2 * hh + 1]));
            rmax = fmaxf(rmax, __shfl_xor_sync(0xffffffffu, rmax, 1));
            rmax = fmaxf(rmax, __shfl_xor_sync(0xffffffffu, rmax, 2));
            float newm = fmaxf(mrow[hh], rmax);
            float alpha = __expf(mrow[hh] - newm);
            mrow[hh] = newm;
            float rsum = 0.f;
            #pragma unroll
            for (int nt = 0; nt < 8; nt++) {
                float p0 = __expf(s[nt][2 * hh]     - newm);
                float p1 = __expf(s[nt][2 * hh + 1] - newm);
                s[nt][2 * hh] = p0; s[nt][2 * hh + 1] = p1;
                rsum += p0 + p1;
                o[nt][2 * hh]     *= alpha;
                o[nt][2 * hh + 1] *= alpha;
            }
            rsum += __shfl_xor_sync(0xffffffffu, rsum, 1);
            rsum += __shfl_xor_sync(0xffffffffu, rsum, 2);
            lrow[hh] = lrow[hh] * alpha + rsum;
        }

        // ---- P to warp-private smem (tf32-rounded), then O += P @ V ----
        {
            float* pw = &sm[OFF_P + wid * 16 * KST];
            #pragma unroll
            for (int nt = 0; nt < 8; nt++) {
                float2 p0; p0.x = rnd_tf32(s[nt][0]); p0.y = rnd_tf32(s[nt][1]);
                float2 p1; p1.x = rnd_tf32(s[nt][2]); p1.y = rnd_tf32(s[nt][3]);
                *reinterpret_cast<float2*>(&pw[ g      * KST + nt * 8 + 2 * t4]) = p0;
                *reinterpret_cast<float2*>(&pw[(g + 8) * KST + nt * 8 + 2 * t4]) = p1;
            }
        }
        __syncwarp();
        {
            const unsigned pb = smb + (OFF_P + wid * 16 * KST) * 4;
            const unsigned vb = smb + ((2 + (t & 1)) * KSZ) * 4;
            #pragma unroll
            for (int j = 0; j < 8; j++) {           // k = key dim, 8 per step
                unsigned af[4];
                ldsm4(af[0], af[1], af[2], af[3],
                      pb + (((q2 & 1) * 8 + r8) * KST + (q2 >> 1) * 4 + j * 8) * 4);
                #pragma unroll
                for (int p = 0; p < 4; p++) {
                    unsigned b0, b1, b2, b3;
                    ldsm4(b0, b1, b2, b3,
                          vb + ((p * 16 + (q2 >> 1) * 8 + r8) * KST + (q2 & 1) * 4 + j * 8) * 4);
                    unsigned bf0[2] = {b0, b1}, bf1[2] = {b2, b3};
                    mma8(o[2 * p],     af, bf0);
                    mma8(o[2 * p + 1], af, bf1);
                }
            }
        }
    }

    // ---- normalize + write back (tf32-rounded: feeds Wo GEMM) ----
    #pragma unroll
    for (int hh = 0; hh < 2; hh++) {
        float inv = 1.0f / lrow[hh];
        long long tok = qtok0 + wid * 16 + g + 8 * hh;
        float* op = Og + tok * D_MODEL + hoff;
        #pragma unroll
        for (int nt = 0; nt < 8; nt++) {
            float2 w;
            w.x = rnd_tf32(o[nt][2 * hh]     * inv);
            w.y = rnd_tf32(o[nt][2 * hh + 1] * inv);
            *reinterpret_cast<float2*>(&op[nt * 8 + 2 * t4]) = w;
        }
    }
}

// ---------------------------------------------------------------------------
// Single-launch tf32 rounding of all weights into g_wr (segment dispatch).
// ---------------------------------------------------------------------------
__global__ void __launch_bounds__(256)
round_all_kernel(const float* __restrict__ Wq, const float* __restrict__ Wk,
                 const float* __restrict__ Wv, const float* __restrict__ Wo,
                 const float* __restrict__ Wup, const float* __restrict__ Wdown,
                 float* __restrict__ dst)
{
    long long i = (long long)blockIdx.x * 256 + threadIdx.x;   // float4 index
    long long f = i;
    const float* s;
    if      (f < 262144)  { s = Wq; }
    else if (f < 524288)  { s = Wk;    f -= 262144; }
    else if (f < 786432)  { s = Wv;    f -= 524288; }
    else if (f < 1048576) { s = Wo;    f -= 786432; }
    else if (f < 2097152) { s = Wup;   f -= 1048576; }
    else                  { s = Wdown; f -= 2097152; }
    float4 v = reinterpret_cast<const float4*>(s)[f];
    v.x = rnd_tf32(v.x); v.y = rnd_tf32(v.y);
    v.z = rnd_tf32(v.z); v.w = rnd_tf32(v.w);
    reinterpret_cast<float4*>(dst)[i] = v;
}

// ---------------------------------------------------------------------------
// LayerNorm (torch-style unbiased var). Output tf32-rounded.
// ---------------------------------------------------------------------------
__global__ void __launch_bounds__(256)
ln_kernel(const float* __restrict__ X, float* __restrict__ Y,
          const float* __restrict__ MS, const float* __restrict__ SS)
{
    __shared__ float shs[8], shq[8];
    const int tid = threadIdx.x;
    const long long base = (long long)blockIdx.x * D_MODEL;
    float4 v = reinterpret_cast<const float4*>(X + base)[tid];
    float s = v.x + v.y + v.z + v.w;
    float qq = v.x * v.x + v.y * v.y + v.z * v.z + v.w * v.w;
    s = warpsum(s); qq = warpsum(qq);
    if ((tid & 31) == 0) { shs[tid >> 5] = s; shq[tid >> 5] = qq; }
    __syncthreads();
    float ts = 0.f, tq = 0.f;
    #pragma unroll
    for (int i = 0; i < 8; i++) { ts += shs[i]; tq += shq[i]; }
    float mean = ts * (1.0f / D_MODEL);
    float var  = (tq - (float)D_MODEL * mean * mean) * (1.0f / (D_MODEL - 1));
    float rstd = rsqrtf(var + 1e-9f);
    float4 ms = reinterpret_cast<const float4*>(MS)[tid];
    float4 ss = reinterpret_cast<const float4*>(SS)[tid];
    float4 o2;
    o2.x = rnd_tf32((v.x - mean) * rstd * ss.x + ms.x);
    o2.y = rnd_tf32((v.y - mean) * rstd * ss.y + ms.y);
    o2.z = rnd_tf32((v.z - mean) * rstd * ss.z + ms.z);
    o2.w = rnd_tf32((v.w - mean) * rstd * ss.w + ms.w);
    reinterpret_cast<float4*>(Y + base)[tid] = o2;
}

// ---------------------------------------------------------------------------
// kernel_launch
// ---------------------------------------------------------------------------
extern "C" void kernel_launch(void* const* d_in, const int* in_sizes, int n_in,
                              void* d_out, int out_size)
{
    const float* x     = (const float*)d_in[0];
    const float* Wq    = (const float*)d_in[1];
    const float* Wk    = (const float*)d_in[2];
    const float* Wv    = (const float*)d_in[3];
    const float* Wo    = (const float*)d_in[4];
    const float* Wup   = (const float*)d_in[5];
    const float* Wdown = (const float*)d_in[6];
    const float* m1    = (const float*)d_in[7];
    const float* s1    = (const float*)d_in[8];
    const float* m2    = (const float*)d_in[9];
    const float* s2    = (const float*)d_in[10];
    float* out = (float*)d_out;

    float *ln, *qkv, *vt, *pre, *x1, *mid, *wr;
    cudaGetSymbolAddress((void**)&ln,  g_ln);
    cudaGetSymbolAddress((void**)&qkv, g_qkv);
    cudaGetSymbolAddress((void**)&vt,  g_vt);
    cudaGetSymbolAddress((void**)&pre, g_pre);
    cudaGetSymbolAddress((void**)&x1,  g_x1);
    cudaGetSymbolAddress((void**)&mid, g_mid);
    cudaGetSymbolAddress((void**)&wr,  g_wr);

    const long long MM = (long long)D_MODEL * D_MODEL;   // 1M
    float* wqkv = wr;
    float* wo   = wr + 3 * MM;
    float* wu   = wr + 4 * MM;
    float* wd   = wr + 8 * MM;
    float* q = qkv;
    float* k = qkv + (long long)MTOK * D_MODEL;
    float* v = qkv + 2 * (long long)MTOK * D_MODEL;

    constexpr int SMEM_NT = 5 * (128 * 20 + 128 * 20) * 4;   // 102400 B
    cudaFuncSetAttribute(gemm_tf32<128,128,32,64,true,EPI_NONE,true>,
                         cudaFuncAttributeMaxDynamicSharedMemorySize, SMEM_NT);
    cudaFuncSetAttribute(gemm_tf32<128,128,32,64,true,EPI_RES,false>,
                         cudaFuncAttributeMaxDynamicSharedMemorySize, SMEM_NT);
    cudaFuncSetAttribute(gemm_tf32<128,128,32,64,true,EPI_GELU,true>,
                         cudaFuncAttributeMaxDynamicSharedMemorySize, SMEM_NT);
    cudaFuncSetAttribute(flash_attn,
                         cudaFuncAttributeMaxDynamicSharedMemorySize, FLASH_SMEM);

    // 0) round all weights to tf32 (one launch)
    round_all_kernel<<<12288, 256>>>(Wq, Wk, Wv, Wo, Wup, Wdown, wr);

    // 1) LN1
    ln_kernel<<<MTOK, 256>>>(x, ln, m1, s1);

    // 2) QKV = ln @ [Wq|Wk|Wv]^T (one batched launch)
    dim3 gqkv3(D_MODEL / 128, MTOK / 128, 3);
    gemm_tf32<128,128,32,64,true,EPI_NONE,true><<<gqkv3, 256, SMEM_NT>>>(
        ln, wqkv, qkv, nullptr, D_MODEL, D_MODEL, D_MODEL, D_MODEL,
        1, 0, 0, MM, 0, (long long)MTOK * D_MODEL, 0, 1.0f);

    // 3) V -> Vt [bh][d][s]
    dim3 gtv(SEQ / 64, BATCH * NHEADS);
    transpose_v<<<gtv, 256>>>(v, vt);

    // 4) fused causal attention -> pre
    flash_attn<<<(SEQ / 128) * BATCH * NHEADS, 256, FLASH_SMEM>>>(q, k, vt, pre);

    // 5) x1 = x + pre @ Wo^T
    dim3 gproj(D_MODEL / 128, MTOK / 128, 1);
    gemm_tf32<128,128,32,64,true,EPI_RES,false><<<gproj, 256, SMEM_NT>>>(
        pre, wo, x1, x, D_MODEL, D_MODEL, D_MODEL, D_MODEL,
        1, 0,0, 0,0, 0,0, 1.0f);

    // 6) LN2
    ln_kernel<<<MTOK, 256>>>(x1, ln, m2, s2);

    // 7) mid = gelu(ln2 @ Wup^T)
    dim3 gup(DFF / 128, MTOK / 128, 1);
    gemm_tf32<128,128,32,64,true,EPI_GELU,true><<<gup, 256, SMEM_NT>>>(
        ln, wu, mid, nullptr, D_MODEL, D_MODEL, D_MODEL, DFF,
        1, 0,0, 0,0, 0,0, 1.0f);

    // 8) out = x1 + mid @ Wdown^T
    gemm_tf32<128,128,32,64,true,EPI_RES,false><<<gproj, 256, SMEM_NT>>>(
        mid, wd, out, x1, DFF, DFF, DFF, D_MODEL,
        1, 0,0, 0,0, 0,0, 1.0f);
}